// round 9
// baseline (speedup 1.0000x reference)
#include <cuda_runtime.h>
#include <cuda_bf16.h>
#include <math.h>
#include <stddef.h>
#include <stdint.h>

// Problem dims (fixed)
constexpr int B_  = 64;
constexpr int T_  = 512;
constexpr int D_  = 512;
constexpr int H_  = 512;
constexpr int G_  = 2048;              // 4*H gates (i,f,g,o)
constexpr int BT_ = B_ * T_;           // 32768
constexpr size_t BTG_ = (size_t)BT_ * G_;   // 67108864 per direction
constexpr size_t HG_  = (size_t)H_ * G_;    // 1048576
constexpr int BH_ = B_ * H_;           // 32768

constexpr unsigned NBLK_ = 128;        // persistent grid: 64 jtiles x 2 dirs

// Scratch (device globals; referenced ONLY from device code — host-side
// references to __device__ symbols give the host shadow address, the R6 bug).
__device__ float g_zx[2 * 67108864];        // [dir][B*T][G] gate preactivations
__device__ float g_h0[33554432];            // layer-0 output [B][T][2H]
__device__ float g_Ur[2 * 1048576];         // permuted recurrent weights
__device__ float g_state[6 * 32768];        // [dir][h_ping,h_pong,c][B*H]

// bf16-split GEMM operands (B has 2 slots so both W-splits can precede GEMMs)
__device__ __align__(16) __nv_bfloat16 g_Ahi[33554432];      // [M, K<=1024]
__device__ __align__(16) __nv_bfloat16 g_Alo[33554432];
__device__ __align__(16) __nv_bfloat16 g_Bhi[2][2097152];    // [slot][N=2048, K<=1024]
__device__ __align__(16) __nv_bfloat16 g_Blo[2][2097152];

// Software grid barrier state (128 co-resident blocks)
__device__ unsigned g_bar_count = 0;
__device__ volatile unsigned g_bar_phase = 0;

__device__ __forceinline__ void grid_barrier()
{
    __syncthreads();
    if (threadIdx.x == 0) {
        unsigned gen = g_bar_phase;
        __threadfence();
        if (atomicAdd(&g_bar_count, 1u) == NBLK_ - 1u) {
            g_bar_count = 0;
            __threadfence();
            g_bar_phase = gen + 1u;
        } else {
            while (g_bar_phase == gen) __nanosleep(64);
            __threadfence();
        }
    }
    __syncthreads();
}

// ---------------------------------------------------------------------------
// Baseline-PTX helpers (compute_103-safe: ldmatrix + mma.sync + cp.async)
// ---------------------------------------------------------------------------
__device__ __forceinline__ uint32_t smem_u32(const void* p) {
    uint32_t a;
    asm("{ .reg .u64 t; cvta.to.shared.u64 t, %1; cvt.u32.u64 %0, t; }" : "=r"(a) : "l"(p));
    return a;
}

__device__ __forceinline__ void ldsm_x4(uint32_t& r0, uint32_t& r1,
                                        uint32_t& r2, uint32_t& r3, uint32_t addr)
{
    asm volatile("ldmatrix.sync.aligned.m8n8.x4.shared.b16 {%0,%1,%2,%3}, [%4];"
        : "=r"(r0), "=r"(r1), "=r"(r2), "=r"(r3) : "r"(addr));
}

__device__ __forceinline__ void mma_16816(float* c, const uint32_t* a,
                                          uint32_t b0, uint32_t b1)
{
    asm volatile(
        "mma.sync.aligned.m16n8k16.row.col.f32.bf16.bf16.f32 "
        "{%0,%1,%2,%3}, {%4,%5,%6,%7}, {%8,%9}, {%0,%1,%2,%3};"
        : "+f"(c[0]), "+f"(c[1]), "+f"(c[2]), "+f"(c[3])
        : "r"(a[0]), "r"(a[1]), "r"(a[2]), "r"(a[3]), "r"(b0), "r"(b1));
}

__device__ __forceinline__ void cp_async16(uint32_t dst, const void* src) {
    asm volatile("cp.async.cg.shared.global [%0], [%1], 16;" :: "r"(dst), "l"(src));
}
__device__ __forceinline__ void cp_commit() {
    asm volatile("cp.async.commit_group;" ::: "memory");
}
template <int N>
__device__ __forceinline__ void cp_wait() {
    asm volatile("cp.async.wait_group %0;" :: "n"(N) : "memory");
}

// ---------------------------------------------------------------------------
// Split fp32 -> bf16 hi/lo into g_Ahi/g_Alo. srcSel: 0 = ext ptr, 1 = g_h0.
// ---------------------------------------------------------------------------
__global__ void split_kernel(const float4* __restrict__ srcExt, int srcSel, int n4)
{
    int i = blockIdx.x * 256 + threadIdx.x;
    if (i >= n4) return;
    const float4* src = srcSel ? (const float4*)g_h0 : srcExt;
    float4 v = src[i];
    __nv_bfloat16 h0 = __float2bfloat16(v.x);
    __nv_bfloat16 h1 = __float2bfloat16(v.y);
    __nv_bfloat16 h2 = __float2bfloat16(v.z);
    __nv_bfloat16 h3 = __float2bfloat16(v.w);
    __nv_bfloat16 l0 = __float2bfloat16(v.x - __bfloat162float(h0));
    __nv_bfloat16 l1 = __float2bfloat16(v.y - __bfloat162float(h1));
    __nv_bfloat16 l2 = __float2bfloat16(v.z - __bfloat162float(h2));
    __nv_bfloat16 l3 = __float2bfloat16(v.w - __bfloat162float(h3));
    __nv_bfloat162* hp = (__nv_bfloat162*)(g_Ahi + 4 * (size_t)i);
    __nv_bfloat162* lp = (__nv_bfloat162*)(g_Alo + 4 * (size_t)i);
    hp[0] = __nv_bfloat162(h0, h1); hp[1] = __nv_bfloat162(h2, h3);
    lp[0] = __nv_bfloat162(l0, l1); lp[1] = __nv_bfloat162(l2, l3);
}

// Transpose + split W [K, N=2048] fp32 -> g_Bhi/g_Blo[slot] [N, K] bf16
__global__ void splitW_kernel(const float* __restrict__ W, int K, int slot)
{
    int idx = blockIdx.x * 256 + threadIdx.x;      // over K*2048
    if (idx >= K * G_) return;
    int k = idx >> 11;
    int n = idx & 2047;
    float v = W[idx];
    __nv_bfloat16 h = __float2bfloat16(v);
    __nv_bfloat16 l = __float2bfloat16(v - __bfloat162float(h));
    g_Bhi[slot][(size_t)n * K + k] = h;
    g_Blo[slot][(size_t)n * K + k] = l;
}

// ---------------------------------------------------------------------------
// cp.async 3-stage pipelined mma.sync bf16-split GEMM:
// C[M,N] = A[M,K] * B[N,K]^T + bias, fp32. Block tile 128x128, BK=32,
// 512 threads = 16 warps (4m x 4n), warp tile 32x32. 3 passes (hh + hl + lh).
// Dynamic smem: 3 stages x 4 tiles x (128 rows x 40 bf16 = 80B rows).
// ---------------------------------------------------------------------------
constexpr int TILE_B   = 128 * 80;        // 10240 bytes per tile
constexpr int STAGE_B  = 4 * TILE_B;      // 40960
constexpr int GEMM_SMEM_B = 3 * STAGE_B;  // 122880

__device__ __forceinline__ void stage_loads(
    uint32_t sbase, const __nv_bfloat16* __restrict__ Bh,
    const __nv_bfloat16* __restrict__ Bl,
    int bm, int bn, int K, int k0, int tid)
{
    // 512 granules of 16B per tile, 512 threads -> 1 granule per tile each
    int r = tid >> 2, q = tid & 3;
    uint32_t d = sbase + (uint32_t)(r * 80 + q * 16);
    size_t goffA = (size_t)(bm + r) * K + k0 + q * 8;
    size_t goffB = (size_t)(bn + r) * K + k0 + q * 8;
    cp_async16(d + 0 * TILE_B, g_Ahi + goffA);
    cp_async16(d + 1 * TILE_B, g_Alo + goffA);
    cp_async16(d + 2 * TILE_B, Bh + goffB);
    cp_async16(d + 3 * TILE_B, Bl + goffB);
}

__global__ __launch_bounds__(512) void gemm_mma_kernel(
    const float* __restrict__ bias, int zx_slot, int bslot, int K)
{
    extern __shared__ char dsm[];
    const uint32_t sb = smem_u32(dsm);

    const int tid = threadIdx.x;
    const int wid = tid >> 5, lane = tid & 31;
    const int warp_m = wid >> 2;          // 0..3
    const int warp_n = wid & 3;           // 0..3
    const int bn = blockIdx.x * 128;
    const int bm = blockIdx.y * 128;
    float* C = g_zx + (size_t)zx_slot * BTG_;
    const __nv_bfloat16* Bh = g_Bhi[bslot];
    const __nv_bfloat16* Bl = g_Blo[bslot];

    float acc[2][4][4];
    #pragma unroll
    for (int mt = 0; mt < 2; mt++)
        #pragma unroll
        for (int nt = 0; nt < 4; nt++)
            #pragma unroll
            for (int q = 0; q < 4; q++) acc[mt][nt][q] = 0.0f;

    // ldmatrix source addressing (within-tile row/col, element units)
    const int a_row = warp_m * 32 + (lane & 15);        // + mt*16
    const int a_col = (lane >> 4) * 8;                  // + k16
    const int b_row = warp_n * 32 + (lane & 7) + ((lane >> 4) & 1) * 8;  // + np*16
    const int b_col = ((lane >> 3) & 1) * 8;            // + k16

    const int nchunk = K / 32;

    // Prefetch stages 0 and 1
    stage_loads(sb + 0 * STAGE_B, Bh, Bl, bm, bn, K, 0, tid);
    cp_commit();
    stage_loads(sb + 1 * STAGE_B, Bh, Bl, bm, bn, K, 32, tid);
    cp_commit();

    int stg_idx = 0;
    for (int ch = 0; ch < nchunk; ch++) {
        if (ch + 2 < nchunk) {
            int wr = stg_idx + 2; if (wr >= 3) wr -= 3;
            stage_loads(sb + wr * STAGE_B, Bh, Bl, bm, bn, K, (ch + 2) * 32, tid);
            cp_commit();
            cp_wait<2>();        // stage ch complete (two newer pending)
        } else if (ch + 1 < nchunk) {
            cp_wait<1>();
        } else {
            cp_wait<0>();
        }
        __syncthreads();

        const uint32_t stg = sb + stg_idx * STAGE_B;
        const uint32_t ahi_b = stg;
        const uint32_t alo_b = stg + 1 * TILE_B;
        const uint32_t bhi_b = stg + 2 * TILE_B;
        const uint32_t blo_b = stg + 3 * TILE_B;

        #pragma unroll
        for (int kk = 0; kk < 2; kk++) {
            const int k16 = kk * 16;
            uint32_t ahi[2][4], alo[2][4];
            #pragma unroll
            for (int mt = 0; mt < 2; mt++) {
                uint32_t off = (uint32_t)((a_row + mt * 16) * 40 + k16 + a_col) * 2;
                ldsm_x4(ahi[mt][0], ahi[mt][1], ahi[mt][2], ahi[mt][3], ahi_b + off);
                ldsm_x4(alo[mt][0], alo[mt][1], alo[mt][2], alo[mt][3], alo_b + off);
            }
            uint32_t bh[4][2], bl[4][2];
            #pragma unroll
            for (int np = 0; np < 2; np++) {
                uint32_t off = (uint32_t)((b_row + np * 16) * 40 + k16 + b_col) * 2;
                ldsm_x4(bh[np*2][0], bh[np*2][1], bh[np*2+1][0], bh[np*2+1][1], bhi_b + off);
                ldsm_x4(bl[np*2][0], bl[np*2][1], bl[np*2+1][0], bl[np*2+1][1], blo_b + off);
            }
            #pragma unroll
            for (int mt = 0; mt < 2; mt++)
                #pragma unroll
                for (int nt = 0; nt < 4; nt++) {
                    mma_16816(acc[mt][nt], ahi[mt], bh[nt][0], bh[nt][1]);
                    mma_16816(acc[mt][nt], ahi[mt], bl[nt][0], bl[nt][1]);
                    mma_16816(acc[mt][nt], alo[mt], bh[nt][0], bh[nt][1]);
                }
        }
        __syncthreads();
        if (++stg_idx == 3) stg_idx = 0;
    }

    // Epilogue: c fragment (m16n8): c0,c1 -> (row + lane/4, col + 2*(lane%4));
    // c2,c3 -> row+8.
    #pragma unroll
    for (int mt = 0; mt < 2; mt++) {
        const int row0 = bm + warp_m * 32 + mt * 16 + (lane >> 2);
        #pragma unroll
        for (int nt = 0; nt < 4; nt++) {
            const int col = bn + warp_n * 32 + nt * 8 + (lane & 3) * 2;
            const float bv0 = bias[col], bv1 = bias[col + 1];
            float2 v0, v1;
            v0.x = acc[mt][nt][0] + bv0; v0.y = acc[mt][nt][1] + bv1;
            v1.x = acc[mt][nt][2] + bv0; v1.y = acc[mt][nt][3] + bv1;
            *(float2*)&C[(size_t)row0 * G_ + col]       = v0;
            *(float2*)&C[(size_t)(row0 + 8) * G_ + col] = v1;
        }
    }
}

// ---------------------------------------------------------------------------
// Permute recurrent weights U[H=512][G=2048] -> g_Ur[slot][jt][k][32]
// ---------------------------------------------------------------------------
__global__ void permute_U_kernel(const float* __restrict__ U, int slot)
{
    int idx = blockIdx.x * 256 + threadIdx.x;    // over 512*2048
    int k = idx >> 11;
    int g = idx & 2047;
    int gate = g >> 9;
    int j = g & 511;
    int jt = j >> 3, jj = j & 7;
    g_Ur[(size_t)slot * HG_ + ((size_t)jt * 512 + k) * 32 + gate * 8 + jj] = U[idx];
}

__global__ void zero_state_kernel()
{
    int i = blockIdx.x * 256 + threadIdx.x;
    if (i < 6 * BH_) g_state[i] = 0.0f;
}

// ---------------------------------------------------------------------------
// Persistent recurrent kernel (unchanged — known good)
// ---------------------------------------------------------------------------
__global__ __launch_bounds__(256) void lstm_seq_kernel(float* __restrict__ outp)
{
    const int dir = blockIdx.y;
    const int jt  = blockIdx.x;
    const int tid = threadIdx.x;
    const int jj  = tid & 7;
    const int bb  = tid >> 3;

    __shared__ float h_s[64][36];
    __shared__ float U_s[32][36];

    float* out = outp ? outp : g_h0;

    const float* zx_d = g_zx + (size_t)dir * BTG_;
    const float* U_d  = g_Ur + (size_t)dir * HG_ + (size_t)jt * (512 * 32);
    float* hbase = g_state + (size_t)dir * 3 * BH_;
    float* cst   = hbase + (size_t)2 * BH_;
    const int j = jt * 8 + jj;

    for (int t = 0; t < T_; t++) {
        const int tt = dir ? (T_ - 1 - t) : t;
        const float* hprev = hbase + (size_t)(t & 1) * BH_;
        float* hnext = hbase + (size_t)((t + 1) & 1) * BH_;

        float acc[2][4];
        #pragma unroll
        for (int r = 0; r < 2; r++)
            #pragma unroll
            for (int g = 0; g < 4; g++) acc[r][g] = 0.0f;

        for (int k0 = 0; k0 < H_; k0 += 32) {
            #pragma unroll
            for (int p = 0; p < 8; p++) {
                int idx = tid + p * 256;
                int b = idx >> 5, kk = idx & 31;
                h_s[b][kk] = hprev[b * H_ + k0 + kk];
            }
            {
                int kk = tid >> 5, c = tid & 31;
                #pragma unroll
                for (int p = 0; p < 4; p++)
                    U_s[c][kk + p * 8] = U_d[(k0 + kk + p * 8) * 32 + c];
            }
            __syncthreads();

            #pragma unroll
            for (int k = 0; k < 32; k += 4) {
                float4 h0v = *(const float4*)&h_s[bb][k];
                float4 h1v = *(const float4*)&h_s[bb + 32][k];
                #pragma unroll
                for (int g = 0; g < 4; g++) {
                    float4 u = *(const float4*)&U_s[g * 8 + jj][k];
                    acc[0][g] += h0v.x * u.x;
                    acc[0][g] += h0v.y * u.y;
                    acc[0][g] += h0v.z * u.z;
                    acc[0][g] += h0v.w * u.w;
                    acc[1][g] += h1v.x * u.x;
                    acc[1][g] += h1v.y * u.y;
                    acc[1][g] += h1v.z * u.z;
                    acc[1][g] += h1v.w * u.w;
                }
            }
            __syncthreads();
        }

        #pragma unroll
        for (int r = 0; r < 2; r++) {
            int b = bb + r * 32;
            const float* zp = zx_d + ((size_t)b * T_ + tt) * G_;
            float zi = acc[r][0] + zp[0 * H_ + j];
            float zf = acc[r][1] + zp[1 * H_ + j];
            float zg = acc[r][2] + zp[2 * H_ + j];
            float zo = acc[r][3] + zp[3 * H_ + j];
            float ig = 1.0f / (1.0f + expf(-zi));
            float fg = 1.0f / (1.0f + expf(-zf));
            float gg = tanhf(zg);
            float og = 1.0f / (1.0f + expf(-zo));
            float cn = fg * cst[b * H_ + j] + ig * gg;
            float hn = og * tanhf(cn);
            cst[b * H_ + j] = cn;
            hnext[b * H_ + j] = hn;
            out[((size_t)b * T_ + tt) * (2 * H_) + dir * H_ + j] = hn;
        }

        grid_barrier();
    }
}

// ---------------------------------------------------------------------------
extern "C" void kernel_launch(void* const* d_in, const int* in_sizes, int n_in,
                              void* d_out, int out_size)
{
    (void)in_sizes; (void)n_in; (void)out_size;
    const float* x   = (const float*)d_in[0];
    const float* W0f = (const float*)d_in[1];
    const float* U0f = (const float*)d_in[2];
    const float* b0f = (const float*)d_in[3];
    const float* W0b = (const float*)d_in[4];
    const float* U0b = (const float*)d_in[5];
    const float* b0b = (const float*)d_in[6];
    const float* W1f = (const float*)d_in[7];
    const float* U1f = (const float*)d_in[8];
    const float* b1f = (const float*)d_in[9];
    const float* W1b = (const float*)d_in[10];
    const float* U1b = (const float*)d_in[11];
    const float* b1b = (const float*)d_in[12];
    float* out = (float*)d_out;

    // Opt-in to 120KB dynamic smem (idempotent; not an allocation)
    cudaFuncSetAttribute(gemm_mma_kernel,
                         cudaFuncAttributeMaxDynamicSharedMemorySize, GEMM_SMEM_B);

    dim3 gemmGrid(G_ / 128, BT_ / 128);   // (16, 256)
    dim3 seqGrid(64, 2);

    // ---- Phase 0: layer 0 (input = x, K = 512) ----
    // Launch order puts gemm_mma as the 6th launch so ncu (-s 5 -c 1)
    // profiles the GEMM instead of a trivial prep kernel.
    {
        const int n4 = (BT_ * D_) / 4;
        split_kernel<<<(n4 + 255) / 256, 256>>>((const float4*)x, /*srcSel=*/0, n4);  // 1
        splitW_kernel<<<(D_ * G_ + 255) / 256, 256>>>(W0f, D_, 0);                    // 2
        splitW_kernel<<<(D_ * G_ + 255) / 256, 256>>>(W0b, D_, 1);                    // 3
        permute_U_kernel<<<4096, 256>>>(U0f, 0);                                      // 4
        permute_U_kernel<<<4096, 256>>>(U0b, 1);                                      // 5
        gemm_mma_kernel<<<gemmGrid, 512, GEMM_SMEM_B>>>(b0f, 0, 0, D_);               // 6
        gemm_mma_kernel<<<gemmGrid, 512, GEMM_SMEM_B>>>(b0b, 1, 1, D_);               // 7
        zero_state_kernel<<<768, 256>>>();                                            // 8
        lstm_seq_kernel<<<seqGrid, 256>>>((float*)nullptr);   // 9: writes g_h0
    }

    // ---- Phase 1: layer 1 (input = g_h0, K = 1024) ----
    {
        const int K1 = 2 * H_;
        const int n4 = (BT_ * K1) / 4;
        split_kernel<<<(n4 + 255) / 256, 256>>>((const float4*)nullptr, /*srcSel=*/1, n4);
        splitW_kernel<<<(K1 * G_ + 255) / 256, 256>>>(W1f, K1, 0);
        splitW_kernel<<<(K1 * G_ + 255) / 256, 256>>>(W1b, K1, 1);
        permute_U_kernel<<<4096, 256>>>(U1f, 0);
        permute_U_kernel<<<4096, 256>>>(U1b, 1);
        gemm_mma_kernel<<<gemmGrid, 512, GEMM_SMEM_B>>>(b1f, 0, 0, K1);
        gemm_mma_kernel<<<gemmGrid, 512, GEMM_SMEM_B>>>(b1b, 1, 1, K1);
        zero_state_kernel<<<768, 256>>>();
        lstm_seq_kernel<<<seqGrid, 256>>>(out);               // writes d_out
    }
}

// round 10
// speedup vs baseline: 1.1683x; 1.1683x over previous
#include <cuda_runtime.h>
#include <cuda_fp16.h>
#include <math.h>
#include <stddef.h>
#include <stdint.h>

// Problem dims (fixed)
constexpr int B_  = 64;
constexpr int T_  = 512;
constexpr int D_  = 512;
constexpr int H_  = 512;
constexpr int G_  = 2048;              // 4*H gates (i,f,g,o)
constexpr int BT_ = B_ * T_;           // 32768
constexpr size_t BTG_ = (size_t)BT_ * G_;   // 67108864 per direction
constexpr size_t HG_  = (size_t)H_ * G_;    // 1048576
constexpr int BH_ = B_ * H_;           // 32768

constexpr unsigned NBLK_ = 128;        // persistent grid: 64 jtiles x 2 dirs

// Scratch (device globals; referenced ONLY from device code — host-side
// references to __device__ symbols give the host shadow address, the R6 bug).
__device__ float g_zx[2 * 67108864];        // [dir][B*T][G] gate preactivations
__device__ float g_h0[33554432];            // layer-0 output [B][T][2H]
__device__ float g_Ur[2 * 1048576];         // permuted recurrent weights
__device__ float g_state[6 * 32768];        // [dir][h_ping,h_pong,c][B*H]

// fp16 single-pass GEMM operands (B has 2 slots so prep precedes both GEMMs)
__device__ __align__(16) __half g_Ah[33554432];      // [M, K<=1024]
__device__ __align__(16) __half g_Bh[2][2097152];    // [slot][N=2048, K<=1024]

// Software grid barrier state (128 co-resident blocks)
__device__ unsigned g_bar_count = 0;
__device__ volatile unsigned g_bar_phase = 0;

__device__ __forceinline__ void grid_barrier()
{
    __syncthreads();
    if (threadIdx.x == 0) {
        unsigned gen = g_bar_phase;
        __threadfence();
        if (atomicAdd(&g_bar_count, 1u) == NBLK_ - 1u) {
            g_bar_count = 0;
            __threadfence();
            g_bar_phase = gen + 1u;
        } else {
            while (g_bar_phase == gen) __nanosleep(64);
            __threadfence();
        }
    }
    __syncthreads();
}

// ---------------------------------------------------------------------------
// Baseline-PTX helpers (compute_103-safe: ldmatrix + mma.sync + cp.async)
// ---------------------------------------------------------------------------
__device__ __forceinline__ uint32_t smem_u32(const void* p) {
    uint32_t a;
    asm("{ .reg .u64 t; cvta.to.shared.u64 t, %1; cvt.u32.u64 %0, t; }" : "=r"(a) : "l"(p));
    return a;
}

__device__ __forceinline__ void ldsm_x4(uint32_t& r0, uint32_t& r1,
                                        uint32_t& r2, uint32_t& r3, uint32_t addr)
{
    asm volatile("ldmatrix.sync.aligned.m8n8.x4.shared.b16 {%0,%1,%2,%3}, [%4];"
        : "=r"(r0), "=r"(r1), "=r"(r2), "=r"(r3) : "r"(addr));
}

__device__ __forceinline__ void mma_16816_f16(float* c, const uint32_t* a,
                                              uint32_t b0, uint32_t b1)
{
    asm volatile(
        "mma.sync.aligned.m16n8k16.row.col.f32.f16.f16.f32 "
        "{%0,%1,%2,%3}, {%4,%5,%6,%7}, {%8,%9}, {%0,%1,%2,%3};"
        : "+f"(c[0]), "+f"(c[1]), "+f"(c[2]), "+f"(c[3])
        : "r"(a[0]), "r"(a[1]), "r"(a[2]), "r"(a[3]), "r"(b0), "r"(b1));
}

__device__ __forceinline__ void cp_async16(uint32_t dst, const void* src) {
    asm volatile("cp.async.cg.shared.global [%0], [%1], 16;" :: "r"(dst), "l"(src));
}
__device__ __forceinline__ void cp_commit() {
    asm volatile("cp.async.commit_group;" ::: "memory");
}
template <int N>
__device__ __forceinline__ void cp_wait() {
    asm volatile("cp.async.wait_group %0;" :: "n"(N) : "memory");
}

// Packed fp32x2 FMA (sm_100-family baseline PTX; exact fp32 math, 2 lanes/instr)
#define FMA2(acc, a, b) \
    asm("fma.rn.f32x2 %0, %1, %2, %0;" : "+l"(acc) : "l"(a), "l"(b))

// ---------------------------------------------------------------------------
// Convert fp32 -> fp16 into g_Ah. srcSel: 0 = ext ptr, 1 = g_h0.
// ---------------------------------------------------------------------------
__global__ void convertA_kernel(const float4* __restrict__ srcExt, int srcSel, int n4)
{
    int i = blockIdx.x * 256 + threadIdx.x;
    if (i >= n4) return;
    const float4* src = srcSel ? (const float4*)g_h0 : srcExt;
    float4 v = src[i];
    __half2* hp = (__half2*)(g_Ah + 4 * (size_t)i);
    hp[0] = __half2(__float2half_rn(v.x), __float2half_rn(v.y));
    hp[1] = __half2(__float2half_rn(v.z), __float2half_rn(v.w));
}

// Transpose + convert W [K, N=2048] fp32 -> g_Bh[slot] [N, K] fp16
__global__ void convertW_kernel(const float* __restrict__ W, int K, int slot)
{
    int idx = blockIdx.x * 256 + threadIdx.x;      // over K*2048
    if (idx >= K * G_) return;
    int k = idx >> 11;
    int n = idx & 2047;
    g_Bh[slot][(size_t)n * K + k] = __float2half_rn(W[idx]);
}

// ---------------------------------------------------------------------------
// cp.async double-buffered single-pass fp16 mma GEMM:
// C[M,N] = A[M,K] * B[N,K]^T + bias, fp32 accum. Block tile 128x128, BK=32,
// 256 threads = 8 warps (2m x 4n), warp tile 64x32.
// Dynamic smem: 2 stages x 2 tiles x (128 rows x 40 halves = 80B rows).
// ---------------------------------------------------------------------------
constexpr int TILE_B   = 128 * 80;        // 10240 bytes per tile
constexpr int STAGE_B  = 2 * TILE_B;      // 20480
constexpr int GEMM_SMEM_B = 2 * STAGE_B;  // 40960

__device__ __forceinline__ void stage_loads(
    uint32_t sbase, const __half* __restrict__ Bp,
    int bm, int bn, int K, int k0, int tid)
{
    #pragma unroll
    for (int it = 0; it < 2; it++) {
        int idx = tid + it * 256;          // 0..511 granules of 16B per tile
        int r = idx >> 2, q = idx & 3;
        uint32_t d = sbase + (uint32_t)(r * 80 + q * 16);
        cp_async16(d + 0 * TILE_B, g_Ah + (size_t)(bm + r) * K + k0 + q * 8);
        cp_async16(d + 1 * TILE_B, Bp   + (size_t)(bn + r) * K + k0 + q * 8);
    }
}

__global__ __launch_bounds__(256) void gemm_mma_kernel(
    const float* __restrict__ bias, int zx_slot, int bslot, int K)
{
    extern __shared__ char dsm[];
    const uint32_t sb = smem_u32(dsm);

    const int tid = threadIdx.x;
    const int wid = tid >> 5, lane = tid & 31;
    const int warp_m = wid >> 2;          // 0..1
    const int warp_n = wid & 3;           // 0..3
    const int bn = blockIdx.x * 128;
    const int bm = blockIdx.y * 128;
    float* C = g_zx + (size_t)zx_slot * BTG_;
    const __half* Bp = g_Bh[bslot];

    float acc[4][4][4];
    #pragma unroll
    for (int mt = 0; mt < 4; mt++)
        #pragma unroll
        for (int nt = 0; nt < 4; nt++)
            #pragma unroll
            for (int q = 0; q < 4; q++) acc[mt][nt][q] = 0.0f;

    // ldmatrix source addressing (within-tile row/col, element units)
    const int a_row = warp_m * 64 + (lane & 15);        // + mt*16
    const int a_col = (lane >> 4) * 8;                  // + k16
    const int b_row = warp_n * 32 + (lane & 7) + ((lane >> 4) & 1) * 8;  // + np*16
    const int b_col = ((lane >> 3) & 1) * 8;            // + k16

    const int nchunk = K / 32;

    // Prefetch stage 0
    stage_loads(sb, Bp, bm, bn, K, 0, tid);
    cp_commit();

    for (int ch = 0; ch < nchunk; ch++) {
        if (ch + 1 < nchunk) {
            stage_loads(sb + ((ch + 1) & 1) * STAGE_B, Bp, bm, bn, K, (ch + 1) * 32, tid);
            cp_commit();
            cp_wait<1>();        // stage ch complete (next stage still pending)
        } else {
            cp_wait<0>();
        }
        __syncthreads();

        const uint32_t stg = sb + (ch & 1) * STAGE_B;
        const uint32_t a_b = stg;
        const uint32_t b_b = stg + TILE_B;

        #pragma unroll
        for (int kk = 0; kk < 2; kk++) {
            const int k16 = kk * 16;
            uint32_t af[4][4];
            #pragma unroll
            for (int mt = 0; mt < 4; mt++) {
                uint32_t off = (uint32_t)((a_row + mt * 16) * 40 + k16 + a_col) * 2;
                ldsm_x4(af[mt][0], af[mt][1], af[mt][2], af[mt][3], a_b + off);
            }
            uint32_t bf[4][2];
            #pragma unroll
            for (int np = 0; np < 2; np++) {
                uint32_t off = (uint32_t)((b_row + np * 16) * 40 + k16 + b_col) * 2;
                ldsm_x4(bf[np*2][0], bf[np*2][1], bf[np*2+1][0], bf[np*2+1][1], b_b + off);
            }
            #pragma unroll
            for (int mt = 0; mt < 4; mt++)
                #pragma unroll
                for (int nt = 0; nt < 4; nt++)
                    mma_16816_f16(acc[mt][nt], af[mt], bf[nt][0], bf[nt][1]);
        }
        __syncthreads();
    }

    // Epilogue: c fragment (m16n8): c0,c1 -> (row + lane/4, col + 2*(lane%4));
    // c2,c3 -> row+8.
    #pragma unroll
    for (int mt = 0; mt < 4; mt++) {
        const int row0 = bm + warp_m * 64 + mt * 16 + (lane >> 2);
        #pragma unroll
        for (int nt = 0; nt < 4; nt++) {
            const int col = bn + warp_n * 32 + nt * 8 + (lane & 3) * 2;
            const float bv0 = bias[col], bv1 = bias[col + 1];
            float2 v0, v1;
            v0.x = acc[mt][nt][0] + bv0; v0.y = acc[mt][nt][1] + bv1;
            v1.x = acc[mt][nt][2] + bv0; v1.y = acc[mt][nt][3] + bv1;
            *(float2*)&C[(size_t)row0 * G_ + col]       = v0;
            *(float2*)&C[(size_t)(row0 + 8) * G_ + col] = v1;
        }
    }
}

// ---------------------------------------------------------------------------
// Permute recurrent weights U[H=512][G=2048] -> g_Ur[slot][jt][k][32]
// ---------------------------------------------------------------------------
__global__ void permute_U_kernel(const float* __restrict__ U, int slot)
{
    int idx = blockIdx.x * 256 + threadIdx.x;    // over 512*2048
    int k = idx >> 11;
    int g = idx & 2047;
    int gate = g >> 9;
    int j = g & 511;
    int jt = j >> 3, jj = j & 7;
    g_Ur[(size_t)slot * HG_ + ((size_t)jt * 512 + k) * 32 + gate * 8 + jj] = U[idx];
}

__global__ void zero_state_kernel()
{
    int i = blockIdx.x * 256 + threadIdx.x;
    if (i < 6 * BH_) g_state[i] = 0.0f;
}

// ---------------------------------------------------------------------------
// Persistent recurrent kernel. Inner product now uses fma.rn.f32x2 packed
// over k-pairs (even/odd partial sums, reduced at the end) — exact fp32,
// half the FMA instruction count.
// ---------------------------------------------------------------------------
__global__ __launch_bounds__(256) void lstm_seq_kernel(float* __restrict__ outp)
{
    const int dir = blockIdx.y;
    const int jt  = blockIdx.x;
    const int tid = threadIdx.x;
    const int jj  = tid & 7;
    const int bb  = tid >> 3;

    __shared__ float h_s[64][36];
    __shared__ float U_s[32][36];

    float* out = outp ? outp : g_h0;

    const float* zx_d = g_zx + (size_t)dir * BTG_;
    const float* U_d  = g_Ur + (size_t)dir * HG_ + (size_t)jt * (512 * 32);
    float* hbase = g_state + (size_t)dir * 3 * BH_;
    float* cst   = hbase + (size_t)2 * BH_;
    const int j = jt * 8 + jj;

    for (int t = 0; t < T_; t++) {
        const int tt = dir ? (T_ - 1 - t) : t;
        const float* hprev = hbase + (size_t)(t & 1) * BH_;
        float* hnext = hbase + (size_t)((t + 1) & 1) * BH_;

        unsigned long long acc2[2][4];   // packed f32x2 (even-k, odd-k sums)
        #pragma unroll
        for (int r = 0; r < 2; r++)
            #pragma unroll
            for (int g = 0; g < 4; g++) acc2[r][g] = 0ull;

        for (int k0 = 0; k0 < H_; k0 += 32) {
            #pragma unroll
            for (int p = 0; p < 8; p++) {
                int idx = tid + p * 256;
                int b = idx >> 5, kk = idx & 31;
                h_s[b][kk] = hprev[b * H_ + k0 + kk];
            }
            {
                int kk = tid >> 5, c = tid & 31;
                #pragma unroll
                for (int p = 0; p < 4; p++)
                    U_s[c][kk + p * 8] = U_d[(k0 + kk + p * 8) * 32 + c];
            }
            __syncthreads();

            #pragma unroll
            for (int k = 0; k < 32; k += 4) {
                // 16B-aligned: row strides are 144B, k is a multiple of 4
                ulonglong2 h0p = *(const ulonglong2*)&h_s[bb][k];
                ulonglong2 h1p = *(const ulonglong2*)&h_s[bb + 32][k];
                #pragma unroll
                for (int g = 0; g < 4; g++) {
                    ulonglong2 up = *(const ulonglong2*)&U_s[g * 8 + jj][k];
                    FMA2(acc2[0][g], h0p.x, up.x);
                    FMA2(acc2[0][g], h0p.y, up.y);
                    FMA2(acc2[1][g], h1p.x, up.x);
                    FMA2(acc2[1][g], h1p.y, up.y);
                }
            }
            __syncthreads();
        }

        #pragma unroll
        for (int r = 0; r < 2; r++) {
            int b = bb + r * 32;
            float a[4];
            #pragma unroll
            for (int g = 0; g < 4; g++) {
                float lo, hi;
                asm("mov.b64 {%0,%1}, %2;" : "=f"(lo), "=f"(hi) : "l"(acc2[r][g]));
                a[g] = lo + hi;
            }
            const float* zp = zx_d + ((size_t)b * T_ + tt) * G_;
            float zi = a[0] + zp[0 * H_ + j];
            float zf = a[1] + zp[1 * H_ + j];
            float zg = a[2] + zp[2 * H_ + j];
            float zo = a[3] + zp[3 * H_ + j];
            float ig = 1.0f / (1.0f + expf(-zi));
            float fg = 1.0f / (1.0f + expf(-zf));
            float gg = tanhf(zg);
            float og = 1.0f / (1.0f + expf(-zo));
            float cn = fg * cst[b * H_ + j] + ig * gg;
            float hn = og * tanhf(cn);
            cst[b * H_ + j] = cn;
            hnext[b * H_ + j] = hn;
            out[((size_t)b * T_ + tt) * (2 * H_) + dir * H_ + j] = hn;
        }

        grid_barrier();
    }
}

// ---------------------------------------------------------------------------
extern "C" void kernel_launch(void* const* d_in, const int* in_sizes, int n_in,
                              void* d_out, int out_size)
{
    (void)in_sizes; (void)n_in; (void)out_size;
    const float* x   = (const float*)d_in[0];
    const float* W0f = (const float*)d_in[1];
    const float* U0f = (const float*)d_in[2];
    const float* b0f = (const float*)d_in[3];
    const float* W0b = (const float*)d_in[4];
    const float* U0b = (const float*)d_in[5];
    const float* b0b = (const float*)d_in[6];
    const float* W1f = (const float*)d_in[7];
    const float* U1f = (const float*)d_in[8];
    const float* b1f = (const float*)d_in[9];
    const float* W1b = (const float*)d_in[10];
    const float* U1b = (const float*)d_in[11];
    const float* b1b = (const float*)d_in[12];
    float* out = (float*)d_out;

    dim3 gemmGrid(G_ / 128, BT_ / 128);   // (16, 256)
    dim3 seqGrid(64, 2);

    // ---- Phase 0: layer 0 (input = x, K = 512) ----
    // Launches 5 AND 6 are GEMMs so ncu (-s 5 -c 1) profiles a GEMM
    // regardless of its off-by-one.
    {
        const int n4 = (BT_ * D_) / 4;
        convertA_kernel<<<(n4 + 255) / 256, 256>>>((const float4*)x, 0, n4);   // 1
        convertW_kernel<<<(D_ * G_ + 255) / 256, 256>>>(W0f, D_, 0);           // 2
        convertW_kernel<<<(D_ * G_ + 255) / 256, 256>>>(W0b, D_, 1);           // 3
        permute_U_kernel<<<4096, 256>>>(U0f, 0);                               // 4
        gemm_mma_kernel<<<gemmGrid, 256, GEMM_SMEM_B>>>(b0f, 0, 0, D_);        // 5
        gemm_mma_kernel<<<gemmGrid, 256, GEMM_SMEM_B>>>(b0b, 1, 1, D_);        // 6
        permute_U_kernel<<<4096, 256>>>(U0b, 1);                               // 7
        zero_state_kernel<<<768, 256>>>();                                     // 8
        lstm_seq_kernel<<<seqGrid, 256>>>((float*)nullptr);   // 9: writes g_h0
    }

    // ---- Phase 1: layer 1 (input = g_h0, K = 1024) ----
    {
        const int K1 = 2 * H_;
        const int n4 = (BT_ * K1) / 4;
        convertA_kernel<<<(n4 + 255) / 256, 256>>>((const float4*)nullptr, 1, n4);
        convertW_kernel<<<(K1 * G_ + 255) / 256, 256>>>(W1f, K1, 0);
        convertW_kernel<<<(K1 * G_ + 255) / 256, 256>>>(W1b, K1, 1);
        permute_U_kernel<<<4096, 256>>>(U1f, 0);
        gemm_mma_kernel<<<gemmGrid, 256, GEMM_SMEM_B>>>(b1f, 0, 0, K1);
        gemm_mma_kernel<<<gemmGrid, 256, GEMM_SMEM_B>>>(b1b, 1, 1, K1);
        permute_U_kernel<<<4096, 256>>>(U1b, 1);
        zero_state_kernel<<<768, 256>>>();
        lstm_seq_kernel<<<seqGrid, 256>>>(out);               // writes d_out
    }
}

// round 11
// speedup vs baseline: 1.4485x; 1.2398x over previous
#include <cuda_runtime.h>
#include <cuda_fp16.h>
#include <math.h>
#include <stddef.h>
#include <stdint.h>

// Problem dims (fixed)
constexpr int B_  = 64;
constexpr int T_  = 512;
constexpr int D_  = 512;
constexpr int H_  = 512;
constexpr int G_  = 2048;              // 4*H gates (i,f,g,o)
constexpr int BT_ = B_ * T_;           // 32768
constexpr size_t BTG_ = (size_t)BT_ * G_;   // 67108864 per direction
constexpr size_t HG_  = (size_t)H_ * G_;    // 1048576
constexpr int BH_ = B_ * H_;           // 32768

// Scratch (device globals; referenced ONLY from device code — host-side
// references to __device__ symbols give the host shadow address, the R6 bug).
__device__ float g_zx[2 * 67108864];        // [dir][B*T][G] gate preactivations
__device__ float g_h0[33554432];            // layer-0 output [B][T][2H]
__device__ float g_Ur[2 * 1048576];         // permuted recurrent weights
__device__ float g_state[6 * 32768];        // [dir][h_ping,h_pong,c][B*H]

// fp16 single-pass GEMM operands
__device__ __align__(16) __half g_Ah[33554432];      // [M, K<=1024]
__device__ __align__(16) __half g_Bh[2][2097152];    // [slot][N=2048, K<=1024]

// Per-direction software grid barriers (64 co-resident blocks each; padded)
__device__ unsigned g_bar_cnt[2][32];
__device__ volatile unsigned g_bar_ph[2][32];

__device__ __forceinline__ void grid_barrier_dir(int dir)
{
    __syncthreads();
    if (threadIdx.x == 0) {
        unsigned gen = g_bar_ph[dir][0];
        __threadfence();
        if (atomicAdd(&g_bar_cnt[dir][0], 1u) == 63u) {
            g_bar_cnt[dir][0] = 0;
            __threadfence();
            g_bar_ph[dir][0] = gen + 1u;
        } else {
            while (g_bar_ph[dir][0] == gen) __nanosleep(64);
            __threadfence();
        }
    }
    __syncthreads();
}

// ---------------------------------------------------------------------------
// Baseline-PTX helpers (compute_103-safe: ldmatrix + mma.sync + cp.async)
// ---------------------------------------------------------------------------
__device__ __forceinline__ uint32_t smem_u32(const void* p) {
    uint32_t a;
    asm("{ .reg .u64 t; cvta.to.shared.u64 t, %1; cvt.u32.u64 %0, t; }" : "=r"(a) : "l"(p));
    return a;
}

__device__ __forceinline__ void ldsm_x4(uint32_t& r0, uint32_t& r1,
                                        uint32_t& r2, uint32_t& r3, uint32_t addr)
{
    asm volatile("ldmatrix.sync.aligned.m8n8.x4.shared.b16 {%0,%1,%2,%3}, [%4];"
        : "=r"(r0), "=r"(r1), "=r"(r2), "=r"(r3) : "r"(addr));
}

__device__ __forceinline__ void mma_16816_f16(float* c, const uint32_t* a,
                                              uint32_t b0, uint32_t b1)
{
    asm volatile(
        "mma.sync.aligned.m16n8k16.row.col.f32.f16.f16.f32 "
        "{%0,%1,%2,%3}, {%4,%5,%6,%7}, {%8,%9}, {%0,%1,%2,%3};"
        : "+f"(c[0]), "+f"(c[1]), "+f"(c[2]), "+f"(c[3])
        : "r"(a[0]), "r"(a[1]), "r"(a[2]), "r"(a[3]), "r"(b0), "r"(b1));
}

__device__ __forceinline__ void cp_async16(uint32_t dst, const void* src) {
    asm volatile("cp.async.cg.shared.global [%0], [%1], 16;" :: "r"(dst), "l"(src));
}
__device__ __forceinline__ void cp_commit() {
    asm volatile("cp.async.commit_group;" ::: "memory");
}
template <int N>
__device__ __forceinline__ void cp_wait() {
    asm volatile("cp.async.wait_group %0;" :: "n"(N) : "memory");
}

// Packed fp32x2 FMA (sm_100-family baseline PTX; exact fp32 math)
#define FMA2(acc, a, b) \
    asm("fma.rn.f32x2 %0, %1, %2, %0;" : "+l"(acc) : "l"(a), "l"(b))

// ---------------------------------------------------------------------------
// Convert fp32 -> fp16 into g_Ah. srcSel: 0 = ext ptr, 1 = g_h0.
// ---------------------------------------------------------------------------
__global__ void convertA_kernel(const float4* __restrict__ srcExt, int srcSel, int n4)
{
    int i = blockIdx.x * 256 + threadIdx.x;
    if (i >= n4) return;
    const float4* src = srcSel ? (const float4*)g_h0 : srcExt;
    float4 v = src[i];
    __half2* hp = (__half2*)(g_Ah + 4 * (size_t)i);
    hp[0] = __half2(__float2half_rn(v.x), __float2half_rn(v.y));
    hp[1] = __half2(__float2half_rn(v.z), __float2half_rn(v.w));
}

// Transpose + convert both W's [K, N=2048] fp32 -> g_Bh[slot] [N, K] fp16
__global__ void convertW2_kernel(const float* __restrict__ Wf,
                                 const float* __restrict__ Wb, int K)
{
    int slot = blockIdx.y;
    const float* W = slot ? Wb : Wf;
    int idx = blockIdx.x * 256 + threadIdx.x;      // over K*2048
    if (idx >= K * G_) return;
    int k = idx >> 11;
    int n = idx & 2047;
    g_Bh[slot][(size_t)n * K + k] = __float2half_rn(W[idx]);
}

// ---------------------------------------------------------------------------
// cp.async double-buffered single-pass fp16 mma GEMM (unchanged from R10):
// C[M,N] = A[M,K] * B[N,K]^T + bias, fp32 accum. Block tile 128x128, BK=32,
// 256 threads = 8 warps (2m x 4n), warp tile 64x32.
// ---------------------------------------------------------------------------
constexpr int TILE_B   = 128 * 80;        // 10240 bytes per tile
constexpr int STAGE_B  = 2 * TILE_B;      // 20480
constexpr int GEMM_SMEM_B = 2 * STAGE_B;  // 40960 (<48KB, no opt-in needed)

__device__ __forceinline__ void stage_loads(
    uint32_t sbase, const __half* __restrict__ Bp,
    int bm, int bn, int K, int k0, int tid)
{
    #pragma unroll
    for (int it = 0; it < 2; it++) {
        int idx = tid + it * 256;          // 0..511 granules of 16B per tile
        int r = idx >> 2, q = idx & 3;
        uint32_t d = sbase + (uint32_t)(r * 80 + q * 16);
        cp_async16(d + 0 * TILE_B, g_Ah + (size_t)(bm + r) * K + k0 + q * 8);
        cp_async16(d + 1 * TILE_B, Bp   + (size_t)(bn + r) * K + k0 + q * 8);
    }
}

__global__ __launch_bounds__(256) void gemm_mma_kernel(
    const float* __restrict__ bias, int zx_slot, int bslot, int K)
{
    extern __shared__ char dsm[];
    const uint32_t sb = smem_u32(dsm);

    const int tid = threadIdx.x;
    const int wid = tid >> 5, lane = tid & 31;
    const int warp_m = wid >> 2;          // 0..1
    const int warp_n = wid & 3;           // 0..3
    const int bn = blockIdx.x * 128;
    const int bm = blockIdx.y * 128;
    float* C = g_zx + (size_t)zx_slot * BTG_;
    const __half* Bp = g_Bh[bslot];

    float acc[4][4][4];
    #pragma unroll
    for (int mt = 0; mt < 4; mt++)
        #pragma unroll
        for (int nt = 0; nt < 4; nt++)
            #pragma unroll
            for (int q = 0; q < 4; q++) acc[mt][nt][q] = 0.0f;

    const int a_row = warp_m * 64 + (lane & 15);
    const int a_col = (lane >> 4) * 8;
    const int b_row = warp_n * 32 + (lane & 7) + ((lane >> 4) & 1) * 8;
    const int b_col = ((lane >> 3) & 1) * 8;

    const int nchunk = K / 32;

    stage_loads(sb, Bp, bm, bn, K, 0, tid);
    cp_commit();

    for (int ch = 0; ch < nchunk; ch++) {
        if (ch + 1 < nchunk) {
            stage_loads(sb + ((ch + 1) & 1) * STAGE_B, Bp, bm, bn, K, (ch + 1) * 32, tid);
            cp_commit();
            cp_wait<1>();
        } else {
            cp_wait<0>();
        }
        __syncthreads();

        const uint32_t stg = sb + (ch & 1) * STAGE_B;
        const uint32_t a_b = stg;
        const uint32_t b_b = stg + TILE_B;

        #pragma unroll
        for (int kk = 0; kk < 2; kk++) {
            const int k16 = kk * 16;
            uint32_t af[4][4];
            #pragma unroll
            for (int mt = 0; mt < 4; mt++) {
                uint32_t off = (uint32_t)((a_row + mt * 16) * 40 + k16 + a_col) * 2;
                ldsm_x4(af[mt][0], af[mt][1], af[mt][2], af[mt][3], a_b + off);
            }
            uint32_t bf[4][2];
            #pragma unroll
            for (int np = 0; np < 2; np++) {
                uint32_t off = (uint32_t)((b_row + np * 16) * 40 + k16 + b_col) * 2;
                ldsm_x4(bf[np*2][0], bf[np*2][1], bf[np*2+1][0], bf[np*2+1][1], b_b + off);
            }
            #pragma unroll
            for (int mt = 0; mt < 4; mt++)
                #pragma unroll
                for (int nt = 0; nt < 4; nt++)
                    mma_16816_f16(acc[mt][nt], af[mt], bf[nt][0], bf[nt][1]);
        }
        __syncthreads();
    }

    #pragma unroll
    for (int mt = 0; mt < 4; mt++) {
        const int row0 = bm + warp_m * 64 + mt * 16 + (lane >> 2);
        #pragma unroll
        for (int nt = 0; nt < 4; nt++) {
            const int col = bn + warp_n * 32 + nt * 8 + (lane & 3) * 2;
            const float bv0 = bias[col], bv1 = bias[col + 1];
            float2 v0, v1;
            v0.x = acc[mt][nt][0] + bv0; v0.y = acc[mt][nt][1] + bv1;
            v1.x = acc[mt][nt][2] + bv0; v1.y = acc[mt][nt][3] + bv1;
            *(float2*)&C[(size_t)row0 * G_ + col]       = v0;
            *(float2*)&C[(size_t)(row0 + 8) * G_ + col] = v1;
        }
    }
}

// ---------------------------------------------------------------------------
// Permute both recurrent weights U[H=512][G=2048] -> g_Ur[slot][jt][k][32]
// ---------------------------------------------------------------------------
__global__ void permute_U2_kernel(const float* __restrict__ Uf,
                                  const float* __restrict__ Ub)
{
    int slot = blockIdx.y;
    const float* U = slot ? Ub : Uf;
    int idx = blockIdx.x * 256 + threadIdx.x;    // over 512*2048
    int k = idx >> 11;
    int g = idx & 2047;
    int gate = g >> 9;
    int j = g & 511;
    int jt = j >> 3, jj = j & 7;
    g_Ur[(size_t)slot * HG_ + ((size_t)jt * 512 + k) * 32 + gate * 8 + jj] = U[idx];
}

// ---------------------------------------------------------------------------
// Persistent recurrent kernel, latency-optimized:
//  - U resident in smem (32 cols x 516-padded rows, loaded once)
//  - h tiles cp.async double-buffered within each timestep
//  - zx gate preactivations prefetched at timestep start
//  - per-direction grid barriers
// Dynamic smem: U 66048B + 2 h-stages x 9216B = 84480B.
// ---------------------------------------------------------------------------
constexpr int UPAD = 516;                      // 516 % 32 == 4 -> conflict-free
constexpr int U_F = 32 * UPAD;                 // 16512 floats
constexpr int HSTG_F = 64 * 36;                // 2304 floats per stage
constexpr int LSTM_SMEM_B = (U_F + 2 * HSTG_F) * 4;   // 84480

__global__ __launch_bounds__(256) void lstm_seq_kernel(float* __restrict__ outp)
{
    extern __shared__ float sm[];
    const int dir = blockIdx.y;
    const int jt  = blockIdx.x;
    const int tid = threadIdx.x;
    const int jj  = tid & 7;
    const int bb  = tid >> 3;                  // 0..31

    float* U_s = sm;                           // [32][516]
    float* h_st0 = sm + U_F;                   // [64][36]
    float* h_st1 = sm + U_F + HSTG_F;
    const uint32_t haddr0 = smem_u32(sm) + (uint32_t)(U_F * 4);

    float* out = outp ? outp : g_h0;
    const float* zx_d = g_zx + (size_t)dir * BTG_;
    const float* U_d  = g_Ur + (size_t)dir * HG_ + (size_t)jt * (512 * 32);
    float* hbase = g_state + (size_t)dir * 3 * BH_;
    float* cst   = hbase + (size_t)2 * BH_;
    const int j = jt * 8 + jj;

    // Load U resident, transposed to [c][k] (one-time; write conflicts OK)
    #pragma unroll 4
    for (int p = 0; p < 64; p++) {
        int idx = tid + p * 256;
        int k = idx >> 5, c = idx & 31;
        U_s[c * UPAD + k] = U_d[idx];
    }
    // Zero own state slices (h ping slot 0 + c)
    for (int i = tid; i < 512; i += 256) {
        int b = i >> 3, jl = i & 7;
        hbase[b * H_ + jt * 8 + jl] = 0.0f;
        cst[b * H_ + jt * 8 + jl]   = 0.0f;
    }
    __syncthreads();
    grid_barrier_dir(dir);

    for (int t = 0; t < T_; t++) {
        const int tt = dir ? (T_ - 1 - t) : t;
        const float* hprev = hbase + (size_t)(t & 1) * BH_;
        float* hnext = hbase + (size_t)((t + 1) & 1) * BH_;

        // Prefetch zx gate values (latency hides under the K loop)
        float zpre[2][4];
        #pragma unroll
        for (int r = 0; r < 2; r++) {
            const float* zp = zx_d + ((size_t)(bb + r * 32) * T_ + tt) * G_;
            #pragma unroll
            for (int g = 0; g < 4; g++) zpre[r][g] = zp[g * H_ + j];
        }

        // Issue h chunk 0 into stage 0
        #pragma unroll
        for (int it = 0; it < 2; it++) {
            int idx = tid + it * 256;
            int b = idx >> 3, q = idx & 7;
            cp_async16(haddr0 + (uint32_t)(b * 144 + q * 16),
                       hprev + b * H_ + q * 4);
        }
        cp_commit();

        unsigned long long acc2[2][4];
        #pragma unroll
        for (int r = 0; r < 2; r++)
            #pragma unroll
            for (int g = 0; g < 4; g++) acc2[r][g] = 0ull;

        for (int ch = 0; ch < 16; ch++) {
            if (ch + 1 < 16) {
                uint32_t ha = haddr0 + (uint32_t)(((ch + 1) & 1) * (HSTG_F * 4));
                const int k0n = (ch + 1) * 32;
                #pragma unroll
                for (int it = 0; it < 2; it++) {
                    int idx = tid + it * 256;
                    int b = idx >> 3, q = idx & 7;
                    cp_async16(ha + (uint32_t)(b * 144 + q * 16),
                               hprev + b * H_ + k0n + q * 4);
                }
                cp_commit();
                cp_wait<1>();
            } else {
                cp_wait<0>();
            }
            __syncthreads();

            const float* hsb = (ch & 1) ? h_st1 : h_st0;
            const float* hs0 = hsb + bb * 36;
            const float* hs1 = hsb + (bb + 32) * 36;
            const int k0 = ch * 32;
            #pragma unroll
            for (int k = 0; k < 32; k += 4) {
                ulonglong2 h0p = *(const ulonglong2*)(hs0 + k);
                ulonglong2 h1p = *(const ulonglong2*)(hs1 + k);
                #pragma unroll
                for (int g = 0; g < 4; g++) {
                    ulonglong2 up = *(const ulonglong2*)(U_s + (g * 8 + jj) * UPAD + k0 + k);
                    FMA2(acc2[0][g], h0p.x, up.x);
                    FMA2(acc2[0][g], h0p.y, up.y);
                    FMA2(acc2[1][g], h1p.x, up.x);
                    FMA2(acc2[1][g], h1p.y, up.y);
                }
            }
            __syncthreads();
        }

        #pragma unroll
        for (int r = 0; r < 2; r++) {
            int b = bb + r * 32;
            float a[4];
            #pragma unroll
            for (int g = 0; g < 4; g++) {
                float lo, hi;
                asm("mov.b64 {%0,%1}, %2;" : "=f"(lo), "=f"(hi) : "l"(acc2[r][g]));
                a[g] = lo + hi;
            }
            float zi = a[0] + zpre[r][0];
            float zf = a[1] + zpre[r][1];
            float zg = a[2] + zpre[r][2];
            float zo = a[3] + zpre[r][3];
            float ig = 1.0f / (1.0f + expf(-zi));
            float fg = 1.0f / (1.0f + expf(-zf));
            float gg = tanhf(zg);
            float og = 1.0f / (1.0f + expf(-zo));
            float cn = fg * cst[b * H_ + j] + ig * gg;
            float hn = og * tanhf(cn);
            cst[b * H_ + j] = cn;
            hnext[b * H_ + j] = hn;
            out[((size_t)b * T_ + tt) * (2 * H_) + dir * H_ + j] = hn;
        }

        grid_barrier_dir(dir);
    }
}

// ---------------------------------------------------------------------------
extern "C" void kernel_launch(void* const* d_in, const int* in_sizes, int n_in,
                              void* d_out, int out_size)
{
    (void)in_sizes; (void)n_in; (void)out_size;
    const float* x   = (const float*)d_in[0];
    const float* W0f = (const float*)d_in[1];
    const float* U0f = (const float*)d_in[2];
    const float* b0f = (const float*)d_in[3];
    const float* W0b = (const float*)d_in[4];
    const float* U0b = (const float*)d_in[5];
    const float* b0b = (const float*)d_in[6];
    const float* W1f = (const float*)d_in[7];
    const float* U1f = (const float*)d_in[8];
    const float* b1f = (const float*)d_in[9];
    const float* W1b = (const float*)d_in[10];
    const float* U1b = (const float*)d_in[11];
    const float* b1b = (const float*)d_in[12];
    float* out = (float*)d_out;

    // Opt-in for 84KB lstm smem (idempotent; not an allocation)
    cudaFuncSetAttribute(lstm_seq_kernel,
                         cudaFuncAttributeMaxDynamicSharedMemorySize, LSTM_SMEM_B);

    dim3 gemmGrid(G_ / 128, BT_ / 128);   // (16, 256)
    dim3 seqGrid(64, 2);

    // ---- Phase 0: layer 0 (input = x, K = 512) ----
    // Launches #3 and #4 are GEMMs (ncu -s 5 -c 1 lands on #3/#4 empirically).
    {
        const int n4 = (BT_ * D_) / 4;
        convertA_kernel<<<(n4 + 255) / 256, 256>>>((const float4*)x, 0, n4);        // 1
        convertW2_kernel<<<dim3((D_ * G_ + 255) / 256, 2), 256>>>(W0f, W0b, D_);    // 2
        gemm_mma_kernel<<<gemmGrid, 256, GEMM_SMEM_B>>>(b0f, 0, 0, D_);             // 3
        gemm_mma_kernel<<<gemmGrid, 256, GEMM_SMEM_B>>>(b0b, 1, 1, D_);             // 4
        permute_U2_kernel<<<dim3(4096, 2), 256>>>(U0f, U0b);                        // 5
        lstm_seq_kernel<<<seqGrid, 256, LSTM_SMEM_B>>>((float*)nullptr);            // 6
    }

    // ---- Phase 1: layer 1 (input = g_h0, K = 1024) ----
    {
        const int K1 = 2 * H_;
        const int n4 = (BT_ * K1) / 4;
        convertA_kernel<<<(n4 + 255) / 256, 256>>>((const float4*)nullptr, 1, n4);
        convertW2_kernel<<<dim3((K1 * G_ + 255) / 256, 2), 256>>>(W1f, W1b, K1);
        gemm_mma_kernel<<<gemmGrid, 256, GEMM_SMEM_B>>>(b1f, 0, 0, K1);
        gemm_mma_kernel<<<gemmGrid, 256, GEMM_SMEM_B>>>(b1b, 1, 1, K1);
        permute_U2_kernel<<<dim3(4096, 2), 256>>>(U1f, U1b);
        lstm_seq_kernel<<<seqGrid, 256, LSTM_SMEM_B>>>(out);
    }
}

// round 12
// speedup vs baseline: 3.0680x; 2.1181x over previous
#include <cuda_runtime.h>
#include <cuda_fp16.h>
#include <cuda_bf16.h>
#include <math.h>
#include <stddef.h>
#include <stdint.h>

// Problem dims (fixed)
constexpr int B_  = 64;
constexpr int T_  = 512;
constexpr int D_  = 512;
constexpr int H_  = 512;
constexpr int G_  = 2048;              // 4*H gates (i,f,g,o)
constexpr int BT_ = B_ * T_;           // 32768
constexpr size_t BTG_ = (size_t)BT_ * G_;   // 67108864 per direction
constexpr int BH_ = B_ * H_;           // 32768

// Scratch (device globals; referenced ONLY from device code — host-side
// references to __device__ symbols give the host shadow address, the R6 bug).
__device__ float g_zx[2 * 67108864];        // [dir][B*T][G] gate preactivations
__device__ float g_h0[33554432];            // layer-0 output [B][T][2H]

// fp16 single-pass GEMM operands
__device__ __align__(16) __half g_Ah[33554432];      // [M, K<=1024]
__device__ __align__(16) __half g_Bh[2][2097152];    // [slot][N=2048, K<=1024]

// Recurrent h state, bf16 hi/lo, ping-ponged: [dir][ping][hi/lo][B*H]
__device__ __align__(16) __nv_bfloat16 g_hb[2][2][2][32768];

// Per-direction software grid barriers (64 co-resident blocks each; padded)
__device__ unsigned g_bar_cnt[2][32];
__device__ volatile unsigned g_bar_ph[2][32];

__device__ __forceinline__ void grid_barrier_dir(int dir)
{
    __syncthreads();
    if (threadIdx.x == 0) {
        unsigned gen = g_bar_ph[dir][0];
        __threadfence();
        if (atomicAdd(&g_bar_cnt[dir][0], 1u) == 63u) {
            g_bar_cnt[dir][0] = 0;
            __threadfence();
            g_bar_ph[dir][0] = gen + 1u;
        } else {
            while (g_bar_ph[dir][0] == gen) __nanosleep(64);
            __threadfence();
        }
    }
    __syncthreads();
}

// ---------------------------------------------------------------------------
// Baseline-PTX helpers (compute_103-safe: ldmatrix + mma.sync + cp.async)
// ---------------------------------------------------------------------------
__device__ __forceinline__ uint32_t smem_u32(const void* p) {
    uint32_t a;
    asm("{ .reg .u64 t; cvta.to.shared.u64 t, %1; cvt.u32.u64 %0, t; }" : "=r"(a) : "l"(p));
    return a;
}

__device__ __forceinline__ void ldsm_x4(uint32_t& r0, uint32_t& r1,
                                        uint32_t& r2, uint32_t& r3, uint32_t addr)
{
    asm volatile("ldmatrix.sync.aligned.m8n8.x4.shared.b16 {%0,%1,%2,%3}, [%4];"
        : "=r"(r0), "=r"(r1), "=r"(r2), "=r"(r3) : "r"(addr));
}

__device__ __forceinline__ void mma_16816_f16(float* c, const uint32_t* a,
                                              uint32_t b0, uint32_t b1)
{
    asm volatile(
        "mma.sync.aligned.m16n8k16.row.col.f32.f16.f16.f32 "
        "{%0,%1,%2,%3}, {%4,%5,%6,%7}, {%8,%9}, {%0,%1,%2,%3};"
        : "+f"(c[0]), "+f"(c[1]), "+f"(c[2]), "+f"(c[3])
        : "r"(a[0]), "r"(a[1]), "r"(a[2]), "r"(a[3]), "r"(b0), "r"(b1));
}

__device__ __forceinline__ void mma_16816_bf16(float* c, const uint32_t* a,
                                               uint32_t b0, uint32_t b1)
{
    asm volatile(
        "mma.sync.aligned.m16n8k16.row.col.f32.bf16.bf16.f32 "
        "{%0,%1,%2,%3}, {%4,%5,%6,%7}, {%8,%9}, {%0,%1,%2,%3};"
        : "+f"(c[0]), "+f"(c[1]), "+f"(c[2]), "+f"(c[3])
        : "r"(a[0]), "r"(a[1]), "r"(a[2]), "r"(a[3]), "r"(b0), "r"(b1));
}

__device__ __forceinline__ void cp_async16(uint32_t dst, const void* src) {
    asm volatile("cp.async.cg.shared.global [%0], [%1], 16;" :: "r"(dst), "l"(src));
}
__device__ __forceinline__ void cp_commit() {
    asm volatile("cp.async.commit_group;" ::: "memory");
}
template <int N>
__device__ __forceinline__ void cp_wait() {
    asm volatile("cp.async.wait_group %0;" :: "n"(N) : "memory");
}

// ---------------------------------------------------------------------------
// Convert fp32 -> fp16 into g_Ah. srcSel: 0 = ext ptr, 1 = g_h0.
// ---------------------------------------------------------------------------
__global__ void convertA_kernel(const float4* __restrict__ srcExt, int srcSel, int n4)
{
    int i = blockIdx.x * 256 + threadIdx.x;
    if (i >= n4) return;
    const float4* src = srcSel ? (const float4*)g_h0 : srcExt;
    float4 v = src[i];
    __half2* hp = (__half2*)(g_Ah + 4 * (size_t)i);
    hp[0] = __half2(__float2half_rn(v.x), __float2half_rn(v.y));
    hp[1] = __half2(__float2half_rn(v.z), __float2half_rn(v.w));
}

// Transpose + convert both W's [K, N=2048] fp32 -> g_Bh[slot] [N, K] fp16
__global__ void convertW2_kernel(const float* __restrict__ Wf,
                                 const float* __restrict__ Wb, int K)
{
    int slot = blockIdx.y;
    const float* W = slot ? Wb : Wf;
    int idx = blockIdx.x * 256 + threadIdx.x;      // over K*2048
    if (idx >= K * G_) return;
    int k = idx >> 11;
    int n = idx & 2047;
    g_Bh[slot][(size_t)n * K + k] = __float2half_rn(W[idx]);
}

// ---------------------------------------------------------------------------
// cp.async double-buffered single-pass fp16 mma GEMM (proven R10 core).
// gridDim.z = 2 runs fwd/bwd in one launch (bslot = blockIdx.z).
// C[M,N] = A[M,K] * B[N,K]^T + bias. 128x128 tile, BK=32, 8 warps (2m x 4n).
// ---------------------------------------------------------------------------
constexpr int TILE_B   = 128 * 80;        // 10240 bytes per tile
constexpr int STAGE_B  = 2 * TILE_B;      // 20480
constexpr int GEMM_SMEM_B = 2 * STAGE_B;  // 40960 (<48KB, no opt-in needed)

__device__ __forceinline__ void stage_loads(
    uint32_t sbase, const __half* __restrict__ Bp,
    int bm, int bn, int K, int k0, int tid)
{
    #pragma unroll
    for (int it = 0; it < 2; it++) {
        int idx = tid + it * 256;          // 0..511 granules of 16B per tile
        int r = idx >> 2, q = idx & 3;
        uint32_t d = sbase + (uint32_t)(r * 80 + q * 16);
        cp_async16(d + 0 * TILE_B, g_Ah + (size_t)(bm + r) * K + k0 + q * 8);
        cp_async16(d + 1 * TILE_B, Bp   + (size_t)(bn + r) * K + k0 + q * 8);
    }
}

__global__ __launch_bounds__(256) void gemm_mma_kernel(
    const float* __restrict__ bias_f, const float* __restrict__ bias_b, int K)
{
    extern __shared__ char dsm[];
    const uint32_t sb = smem_u32(dsm);

    const int bslot = blockIdx.z;
    const float* bias = bslot ? bias_b : bias_f;
    const int tid = threadIdx.x;
    const int wid = tid >> 5, lane = tid & 31;
    const int warp_m = wid >> 2;          // 0..1
    const int warp_n = wid & 3;           // 0..3
    const int bn = blockIdx.x * 128;
    const int bm = blockIdx.y * 128;
    float* C = g_zx + (size_t)bslot * BTG_;
    const __half* Bp = g_Bh[bslot];

    float acc[4][4][4];
    #pragma unroll
    for (int mt = 0; mt < 4; mt++)
        #pragma unroll
        for (int nt = 0; nt < 4; nt++)
            #pragma unroll
            for (int q = 0; q < 4; q++) acc[mt][nt][q] = 0.0f;

    const int a_row = warp_m * 64 + (lane & 15);
    const int a_col = (lane >> 4) * 8;
    const int b_row = warp_n * 32 + (lane & 7) + ((lane >> 4) & 1) * 8;
    const int b_col = ((lane >> 3) & 1) * 8;

    const int nchunk = K / 32;

    stage_loads(sb, Bp, bm, bn, K, 0, tid);
    cp_commit();

    for (int ch = 0; ch < nchunk; ch++) {
        if (ch + 1 < nchunk) {
            stage_loads(sb + ((ch + 1) & 1) * STAGE_B, Bp, bm, bn, K, (ch + 1) * 32, tid);
            cp_commit();
            cp_wait<1>();
        } else {
            cp_wait<0>();
        }
        __syncthreads();

        const uint32_t stg = sb + (ch & 1) * STAGE_B;
        const uint32_t a_b = stg;
        const uint32_t b_b = stg + TILE_B;

        #pragma unroll
        for (int kk = 0; kk < 2; kk++) {
            const int k16 = kk * 16;
            uint32_t af[4][4];
            #pragma unroll
            for (int mt = 0; mt < 4; mt++) {
                uint32_t off = (uint32_t)((a_row + mt * 16) * 40 + k16 + a_col) * 2;
                ldsm_x4(af[mt][0], af[mt][1], af[mt][2], af[mt][3], a_b + off);
            }
            uint32_t bf[4][2];
            #pragma unroll
            for (int np = 0; np < 2; np++) {
                uint32_t off = (uint32_t)((b_row + np * 16) * 40 + k16 + b_col) * 2;
                ldsm_x4(bf[np*2][0], bf[np*2][1], bf[np*2+1][0], bf[np*2+1][1], b_b + off);
            }
            #pragma unroll
            for (int mt = 0; mt < 4; mt++)
                #pragma unroll
                for (int nt = 0; nt < 4; nt++)
                    mma_16816_f16(acc[mt][nt], af[mt], bf[nt][0], bf[nt][1]);
        }
        __syncthreads();
    }

    #pragma unroll
    for (int mt = 0; mt < 4; mt++) {
        const int row0 = bm + warp_m * 64 + mt * 16 + (lane >> 2);
        #pragma unroll
        for (int nt = 0; nt < 4; nt++) {
            const int col = bn + warp_n * 32 + nt * 8 + (lane & 3) * 2;
            const float bv0 = bias[col], bv1 = bias[col + 1];
            float2 v0, v1;
            v0.x = acc[mt][nt][0] + bv0; v0.y = acc[mt][nt][1] + bv1;
            v1.x = acc[mt][nt][2] + bv0; v1.y = acc[mt][nt][3] + bv1;
            *(float2*)&C[(size_t)row0 * G_ + col]       = v0;
            *(float2*)&C[(size_t)(row0 + 8) * G_ + col] = v1;
        }
    }
}

// ---------------------------------------------------------------------------
// Persistent recurrent kernel, tensor-core edition.
// Grid (64 jt, 2 dir), 256 threads = 8 warps as 4m x 2n (warp tile 16b x 16c).
// Per step: Z[64b x 32c] = Hprev[64 x 512] @ U[512 x 32c], bf16 hi/lo 3-pass
// (hh + hl + lh) via mma.sync; c-state in registers; h ping-pongs in global
// bf16 hi/lo; U resident in smem (converted from raw U at startup).
// ---------------------------------------------------------------------------
constexpr int U_ST = 520;                         // U smem stride (elements)
constexpr int H_ST = 136;                         // h chunk stride (elements)
constexpr int U_COPY_B  = 32 * U_ST * 2;          // 33280 (one of hi/lo)
constexpr int H_COPY_B  = 64 * H_ST * 2;          // 17408 (one of hi/lo)
constexpr int H_STAGE_B = 2 * H_COPY_B;           // 34816
constexpr int SM_H = 2 * U_COPY_B;                // 66560
constexpr int SM_Z = SM_H + 2 * H_STAGE_B;        // 136192
constexpr int LSTM_SMEM_B = SM_Z + 64 * 36 * 4;   // 145408

__device__ __forceinline__ void issue_h(
    uint32_t dst_base, const __nv_bfloat16* __restrict__ hhi,
    const __nv_bfloat16* __restrict__ hlo, int ck, int tid)
{
    #pragma unroll
    for (int it = 0; it < 4; it++) {
        int idx = tid + it * 256;            // 0..1023
        int row = idx >> 4, g = idx & 15;    // 16 granules x 16B = 128 bf16/row
        uint32_t d = dst_base + (uint32_t)(row * 272 + g * 16);
        const size_t s = (size_t)row * H_ + ck * 128 + g * 8;
        cp_async16(d, hhi + s);
        cp_async16(d + H_COPY_B, hlo + s);
    }
}

__global__ __launch_bounds__(256) void lstm_seq_kernel(
    const float* __restrict__ Uf, const float* __restrict__ Ub,
    float* __restrict__ outp)
{
    extern __shared__ char sm[];
    const uint32_t sb = smem_u32(sm);
    const int dir = blockIdx.y;
    const int jt  = blockIdx.x;
    const int tid = threadIdx.x;
    const int wid = tid >> 5, lane = tid & 31;
    const int warp_m = wid >> 1;             // 0..3 (16 batch rows each)
    const int warp_n = wid & 1;              // 0..1 (16 c-cols each)

    __nv_bfloat16* Uhi_s = (__nv_bfloat16*)sm;
    __nv_bfloat16* Ulo_s = Uhi_s + 32 * U_ST;
    float* z_s = (float*)(sm + SM_Z);
    const uint32_t u_hi = sb;
    const uint32_t u_lo = sb + U_COPY_B;
    const uint32_t h_b  = sb + SM_H;

    const float* U_raw = dir ? Ub : Uf;
    float* out = outp ? outp : g_h0;
    const float* zx_d = g_zx + (size_t)dir * BTG_;

    // One-time: load raw U[k][gate*512 + jt*8 + jj] -> smem bf16 hi/lo [c][k]
    #pragma unroll 4
    for (int p = 0; p < 64; p++) {
        int idx = tid + p * 256;             // k*32 + c over 512*32
        int k = idx >> 5, c = idx & 31;
        int gate = c >> 3, jl = c & 7;
        float v = U_raw[(size_t)k * G_ + gate * H_ + jt * 8 + jl];
        __nv_bfloat16 h = __float2bfloat16(v);
        Uhi_s[c * U_ST + k] = h;
        Ulo_s[c * U_ST + k] = __float2bfloat16(v - __bfloat162float(h));
    }
    // Zero own slice of h ping slot 0
    for (int i = tid; i < 512; i += 256) {
        int b = i >> 3, jl = i & 7;
        g_hb[dir][0][0][b * H_ + jt * 8 + jl] = __float2bfloat16(0.0f);
        g_hb[dir][0][1][b * H_ + jt * 8 + jl] = __float2bfloat16(0.0f);
    }
    __syncthreads();
    grid_barrier_dir(dir);

    // c-state in registers: thread owns (b = tid>>3 [+32], jj = tid&7)
    float creg[2] = {0.0f, 0.0f};
    const int jj = tid & 7;
    const int j = jt * 8 + jj;

    // ldmatrix lane addressing (element units)
    const int a_row = warp_m * 16 + (lane & 15);
    const int a_col = (lane >> 4) * 8;
    const int b_row = warp_n * 16 + (lane & 7) + ((lane >> 4) & 1) * 8;
    const int b_col = ((lane >> 3) & 1) * 8;

    for (int t = 0; t < T_; t++) {
        const int tt = dir ? (T_ - 1 - t) : t;
        const int ping = t & 1, pnext = ping ^ 1;
        const __nv_bfloat16* hhi = g_hb[dir][ping][0];
        const __nv_bfloat16* hlo = g_hb[dir][ping][1];

        // Prefetch zx gates (latency hidden under the mma loop)
        float zpre[2][4];
        #pragma unroll
        for (int r = 0; r < 2; r++) {
            const int b = (tid >> 3) + r * 32;
            const float* zp = zx_d + ((size_t)b * T_ + tt) * G_;
            #pragma unroll
            for (int g = 0; g < 4; g++) zpre[r][g] = zp[g * H_ + j];
        }

        issue_h(h_b, hhi, hlo, 0, tid);
        cp_commit();

        float acc[2][4];
        #pragma unroll
        for (int nt = 0; nt < 2; nt++)
            #pragma unroll
            for (int q = 0; q < 4; q++) acc[nt][q] = 0.0f;

        for (int ck = 0; ck < 4; ck++) {
            if (ck + 1 < 4) {
                issue_h(h_b + ((ck + 1) & 1) * H_STAGE_B, hhi, hlo, ck + 1, tid);
                cp_commit();
                cp_wait<1>();
            } else {
                cp_wait<0>();
            }
            __syncthreads();

            const uint32_t ha = h_b + (ck & 1) * H_STAGE_B;
            const uint32_t la = ha + H_COPY_B;
            const int kbase = ck * 128;

            #pragma unroll
            for (int ks = 0; ks < 8; ks++) {
                const int k16 = ks * 16;
                const uint32_t aoff = (uint32_t)(a_row * H_ST + k16 + a_col) * 2;
                uint32_t ahi[4], alo[4];
                ldsm_x4(ahi[0], ahi[1], ahi[2], ahi[3], ha + aoff);
                ldsm_x4(alo[0], alo[1], alo[2], alo[3], la + aoff);
                const uint32_t boff =
                    (uint32_t)(b_row * U_ST + kbase + k16 + b_col) * 2;
                uint32_t bh[4], bl[4];
                ldsm_x4(bh[0], bh[1], bh[2], bh[3], u_hi + boff);
                ldsm_x4(bl[0], bl[1], bl[2], bl[3], u_lo + boff);
                mma_16816_bf16(acc[0], ahi, bh[0], bh[1]);
                mma_16816_bf16(acc[1], ahi, bh[2], bh[3]);
                mma_16816_bf16(acc[0], ahi, bl[0], bl[1]);
                mma_16816_bf16(acc[1], ahi, bl[2], bl[3]);
                mma_16816_bf16(acc[0], alo, bh[0], bh[1]);
                mma_16816_bf16(acc[1], alo, bh[2], bh[3]);
            }
            __syncthreads();
        }

        // Exchange z fragments via smem
        {
            const int r0 = warp_m * 16 + (lane >> 2);
            const int cb = warp_n * 16 + (lane & 3) * 2;
            #pragma unroll
            for (int nt = 0; nt < 2; nt++) {
                const int col = cb + nt * 8;
                float2 v0, v1;
                v0.x = acc[nt][0]; v0.y = acc[nt][1];
                v1.x = acc[nt][2]; v1.y = acc[nt][3];
                *(float2*)&z_s[r0 * 36 + col]       = v0;
                *(float2*)&z_s[(r0 + 8) * 36 + col] = v1;
            }
        }
        __syncthreads();

        // Pointwise LSTM update (c in registers)
        #pragma unroll
        for (int r = 0; r < 2; r++) {
            const int b = (tid >> 3) + r * 32;
            const float zi = z_s[b * 36 + 0 * 8 + jj] + zpre[r][0];
            const float zf = z_s[b * 36 + 1 * 8 + jj] + zpre[r][1];
            const float zg = z_s[b * 36 + 2 * 8 + jj] + zpre[r][2];
            const float zo = z_s[b * 36 + 3 * 8 + jj] + zpre[r][3];
            const float ig = 1.0f / (1.0f + expf(-zi));
            const float fg = 1.0f / (1.0f + expf(-zf));
            const float gg = tanhf(zg);
            const float og = 1.0f / (1.0f + expf(-zo));
            const float cn = fg * creg[r] + ig * gg;
            const float hn = og * tanhf(cn);
            creg[r] = cn;
            out[((size_t)b * T_ + tt) * (2 * H_) + dir * H_ + j] = hn;
            const __nv_bfloat16 hh = __float2bfloat16(hn);
            g_hb[dir][pnext][0][b * H_ + j] = hh;
            g_hb[dir][pnext][1][b * H_ + j] =
                __float2bfloat16(hn - __bfloat162float(hh));
        }

        grid_barrier_dir(dir);
    }
}

// ---------------------------------------------------------------------------
extern "C" void kernel_launch(void* const* d_in, const int* in_sizes, int n_in,
                              void* d_out, int out_size)
{
    (void)in_sizes; (void)n_in; (void)out_size;
    const float* x   = (const float*)d_in[0];
    const float* W0f = (const float*)d_in[1];
    const float* U0f = (const float*)d_in[2];
    const float* b0f = (const float*)d_in[3];
    const float* W0b = (const float*)d_in[4];
    const float* U0b = (const float*)d_in[5];
    const float* b0b = (const float*)d_in[6];
    const float* W1f = (const float*)d_in[7];
    const float* U1f = (const float*)d_in[8];
    const float* b1f = (const float*)d_in[9];
    const float* W1b = (const float*)d_in[10];
    const float* U1b = (const float*)d_in[11];
    const float* b1b = (const float*)d_in[12];
    float* out = (float*)d_out;

    // Opt-in for 142KB lstm smem (idempotent; not an allocation)
    cudaFuncSetAttribute(lstm_seq_kernel,
                         cudaFuncAttributeMaxDynamicSharedMemorySize, LSTM_SMEM_B);

    dim3 gemmGrid(G_ / 128, BT_ / 128, 2);   // (16, 256, 2) — fwd+bwd fused
    dim3 seqGrid(64, 2);

    // ---- Phase 0: layer 0 (input = x, K = 512) ----
    {
        const int n4 = (BT_ * D_) / 4;
        convertA_kernel<<<(n4 + 255) / 256, 256>>>((const float4*)x, 0, n4);      // 1
        convertW2_kernel<<<dim3((D_ * G_ + 255) / 256, 2), 256>>>(W0f, W0b, D_);  // 2
        gemm_mma_kernel<<<gemmGrid, 256, GEMM_SMEM_B>>>(b0f, b0b, D_);            // 3
        lstm_seq_kernel<<<seqGrid, 256, LSTM_SMEM_B>>>(U0f, U0b, (float*)nullptr);// 4
    }

    // ---- Phase 1: layer 1 (input = g_h0, K = 1024) ----
    {
        const int K1 = 2 * H_;
        const int n4 = (BT_ * K1) / 4;
        convertA_kernel<<<(n4 + 255) / 256, 256>>>((const float4*)nullptr, 1, n4);
        convertW2_kernel<<<dim3((K1 * G_ + 255) / 256, 2), 256>>>(W1f, W1b, K1);
        gemm_mma_kernel<<<gemmGrid, 256, GEMM_SMEM_B>>>(b1f, b1b, K1);
        lstm_seq_kernel<<<seqGrid, 256, LSTM_SMEM_B>>>(U1f, U1b, out);
    }
}